// round 4
// baseline (speedup 1.0000x reference)
#include <cuda_runtime.h>
#include <cuda_bf16.h>
#include <cstdint>

// Problem constants
#define BB 16
#define AA 8400
#define GG 64
#define CC 80
#define KK 10
#define CAP 768            // max inside-anchors per (b,g); E[n]~95, huge margin

#define EPSF 1e-9f
#define CPI  0.4052847345693511f   // 4 / pi^2

// Output layout (flattened tuple, float32):
//  [0]     bbox_labels [B,A,4]
//  [OFF1]  cls_oh      [B,A,C]
//  [OFF2]  dist        [B,A,1]
//  [OFF3]  fg          [B,A]
#define OFF0 0
#define OFF1 (BB*AA*4)                 // 537600
#define OFF2 (OFF1 + BB*AA*CC)         // 11289600
#define OFF3 (OFF2 + BB*AA)            // 11424000

// ---------------- scratch (static device globals; no allocation) ----------------
__device__ int                g_cnt[BB*GG];
__device__ unsigned           g_cand[BB*GG*CAP];        // ~3MB
__device__ unsigned long long g_key[BB*AA];             // (ovl_bits<<32)|(~g) per anchor
__device__ float              g_norm[BB*AA];            // per-anchor norm (>=0)
__device__ int                g_maskmode;               // 0=uint8 bytes, 1=32-bit words

// ---------------- init + mask-dtype sniffer ----------------
// Mask is jnp bool; harness stores it as uint8, int32, or float32. Classify from
// the first 256 32-bit words (1024 bytes = the minimum buffer size across modes):
//   word == 0x3F800000 (float 1.0)            -> word mode (float32)
//   word > 1 otherwise (e.g. 0x01010101)      -> byte mode (packed uint8)
//   all words in {0,1}                        -> word mode (int32)
__global__ void k_init(const unsigned* __restrict__ mask_words) {
    int i = blockIdx.x * blockDim.x + threadIdx.x;
    if (i < BB*AA) { g_key[i] = 0ULL; g_norm[i] = 0.0f; }
    if (i < BB*GG) g_cnt[i] = 0;
    if (i < 256) {
        unsigned w = mask_words[i];
        bool isf32   = (w == 0x3F800000u);
        bool isbytes = (w > 1u) && !isf32;
        unsigned bf = __ballot_sync(0xFFFFFFFFu, isbytes);
        unsigned ff = __ballot_sync(0xFFFFFFFFu, isf32);
        if ((i & 31) == 0) {
            if (ff) atomicExch(&g_maskmode, 1);        // float32 -> word mode
            else if (bf) atomicOr(&g_maskmode, 2);     // byte mode (unless float seen)
        }
        if (i == 0) { /* default stays as set by atomics; init below */ }
    }
}
__global__ void k_init0() { g_maskmode = 0; }  // 0 = undecided; resolved in k_init

// ---------------- phase A: inside-anchor filter ----------------
// grid: (ceil(A/256), (B*G)/128), block 256
__global__ void k_phaseA(const float4* __restrict__ gtb,
                         const void* __restrict__ gmask,
                         const float2* __restrict__ anchors) {
    __shared__ float4 sb[128];
    int tid = threadIdx.x;
    int bg0 = blockIdx.y * 128;
    int mode = g_maskmode;   // 2 -> bytes; else (0/1) -> words
    if (tid < 128) {
        int bg = bg0 + tid;
        bool mv;
        if (mode == 2) mv = ((const unsigned char*)gmask)[bg] != 0;
        else           mv = ((const unsigned*)gmask)[bg] != 0;   // int32 0/1 or float 1.0f
        float4 bx = gtb[bg];
        if (!mv) bx.x = 3.0e38f;   // masked-out gt: inside test always fails
        sb[tid] = bx;
    }
    __syncthreads();
    int a = blockIdx.x * 256 + tid;
    if (a >= AA) return;
    float2 an = anchors[a];
    #pragma unroll 4
    for (int j = 0; j < 128; j++) {
        float4 bx = sb[j];
        // strict inequalities: (gt[:2] < anchor) & (gt[2:] > anchor)
        if (bx.x < an.x && bx.y < an.y && bx.z > an.x && bx.w > an.y) {
            int bg = bg0 + j;
            int pos = atomicAdd(&g_cnt[bg], 1);
            if (pos < CAP) g_cand[bg * CAP + pos] = (unsigned)a;
        }
    }
}

// ---------------- phase B: CIoU + align + warp top-K + scatter ----------------
// one warp per (b,g); block 128 threads (4 warps)
__global__ void k_phaseB(const float* __restrict__ scores,
                         const float4* __restrict__ dec,
                         const float4* __restrict__ gtb,
                         const int* __restrict__ glab) {
    int wid = (blockIdx.x * blockDim.x + threadIdx.x) >> 5;
    if (wid >= BB*GG) return;
    int lane = threadIdx.x & 31;
    int b = wid / GG, g = wid % GG;
    int n = g_cnt[wid];
    if (n > CAP) n = CAP;
    if (n == 0) return;

    float4 gb = gtb[wid];
    float w1 = gb.z - gb.x, h1 = gb.w - gb.y;
    float at1 = atanf(w1 / (h1 + EPSF));
    float sx = gb.x + gb.z, sy = gb.y + gb.w;
    int label = glab[wid];
    const float*  srow = scores + (size_t)b * AA * CC;
    const float4* drow = dec    + (size_t)b * AA;

    // per-lane candidate cache (<= CAP/32 = 24 items)
    float lv[24]; float lo[24]; int la[24];
    int m = 0;
    for (int idx = lane; idx < n; idx += 32) {
        unsigned a = g_cand[wid * CAP + idx];
        float4 d = drow[a];
        float xx1 = fmaxf(gb.x, d.x), yy1 = fmaxf(gb.y, d.y);
        float xx2 = fminf(gb.z, d.z), yy2 = fminf(gb.w, d.w);
        float inter = fmaxf(xx2 - xx1, 0.0f) * fmaxf(yy2 - yy1, 0.0f);
        float w2 = d.z - d.x, h2 = d.w - d.y;
        float uni = w1 * h1 + w2 * h2 - inter;
        float iou = inter / (uni + EPSF);
        float cw = fmaxf(gb.z, d.z) - fminf(gb.x, d.x);
        float ch = fmaxf(gb.w, d.w) - fminf(gb.y, d.y);
        float c2 = cw * cw + ch * ch + EPSF;
        float dx = sx - d.x - d.z, dy = sy - d.y - d.w;
        float rho2 = (dx * dx + dy * dy) * 0.25f;
        float dv = at1 - atanf(w2 / (h2 + EPSF));
        float v = CPI * dv * dv;
        float aco = v / (v - iou + 1.0f + EPSF);
        float ciou = iou - (rho2 / c2 + v * aco);
        float alval = 0.0f;
        if (ciou > 0.0f) {
            float s = srow[(size_t)a * CC + label];
            float p3 = ciou * ciou * ciou;
            alval = sqrtf(s) * p3 * p3;     // s^0.5 * relu(ciou)^6
        }
        lv[m] = alval; lo[m] = ciou; la[m] = (int)a; m++;
    }

    // K rounds of warp argmax; value in hi bits, ~anchor in lo bits (lower anchor wins ties)
    float sel_v = 0.0f, sel_o = 0.0f; int sel_a = -1;
    int nsel = 0;
    for (int k = 0; k < KK; k++) {
        float bv = 0.0f, bo = 0.0f; int ba = 0x7fffffff, bi = -1;
        for (int i = 0; i < m; i++) {
            if (lv[i] > 0.0f && (lv[i] > bv || (lv[i] == bv && la[i] < ba))) {
                bv = lv[i]; bo = lo[i]; ba = la[i]; bi = i;
            }
        }
        unsigned long long key = (bv > 0.0f)
            ? (((unsigned long long)__float_as_uint(bv) << 32) |
               (unsigned long long)(0xFFFFFFFFu - (unsigned)ba))
            : 0ULL;
        unsigned long long wkey = key;
        #pragma unroll
        for (int off = 16; off; off >>= 1) {
            unsigned long long o = __shfl_xor_sync(0xFFFFFFFFu, wkey, off);
            if (o > wkey) wkey = o;
        }
        if (wkey == 0ULL) break;
        bool iswin = (key == wkey);
        if (iswin) lv[bi] = 0.0f;                    // consume winner
        unsigned wl = __ballot_sync(0xFFFFFFFFu, iswin);
        int wlane = __ffs(wl) - 1;
        float wv = __uint_as_float((unsigned)(wkey >> 32));
        unsigned wa = 0xFFFFFFFFu - (unsigned)(wkey & 0xFFFFFFFFull);
        float wo = __shfl_sync(0xFFFFFFFFu, bo, wlane);
        if (lane == k) { sel_v = wv; sel_a = (int)wa; sel_o = wo; }
        nsel = k + 1;
    }
    if (nsel == 0) return;

    float max_align = __shfl_sync(0xFFFFFFFFu, sel_v, 0);   // round 0 winner = largest align
    float mo = (lane < nsel) ? sel_o : 0.0f;
    #pragma unroll
    for (int off = 16; off; off >>= 1)
        mo = fmaxf(mo, __shfl_xor_sync(0xFFFFFFFFu, mo, off));

    if (lane < nsel) {
        float nc = sel_v * mo / (max_align + EPSF);          // >= 0
        atomicMax((int*)&g_norm[b * AA + sel_a], __float_as_int(nc));
        unsigned long long mk = ((unsigned long long)__float_as_uint(sel_o) << 32) |
                                (unsigned long long)(0xFFFFFFFFu - (unsigned)g);
        atomicMax(&g_key[b * AA + sel_a], mk);               // argmax over g, ties -> smaller g
    }
}

// ---------------- finalize: one warp per anchor writes all outputs ----------------
__global__ void k_final(float* __restrict__ out,
                        const float4* __restrict__ gtb,
                        const int* __restrict__ glab,
                        const float* __restrict__ gdist) {
    int widx = (blockIdx.x * blockDim.x + threadIdx.x) >> 5;
    if (widx >= BB*AA) return;
    int lane = threadIdx.x & 31;
    int b = widx / AA;

    unsigned long long key = 0ULL; float nv = 0.0f;
    if (lane == 0) { key = g_key[widx]; nv = g_norm[widx]; }
    key = __shfl_sync(0xFFFFFFFFu, key, 0);
    nv  = __shfl_sync(0xFFFFFFFFu, nv, 0);

    bool matched = (key != 0ULL);
    int g = matched ? (int)(0xFFFFFFFFu - (unsigned)(key & 0xFFFFFFFFull)) : 0;

    int cls = -1;
    if (matched) cls = glab[b * GG + g];

    if (lane == 0) {
        float4 bb = make_float4(-1.f, -1.f, -1.f, -1.f);
        float gd = -1.0f;
        if (matched) { bb = gtb[b * GG + g]; gd = gdist[b * GG + g]; }
        ((float4*)(out + OFF0))[widx] = bb;
        out[OFF2 + widx] = gd * nv;       // unmatched: -1 * 0 = -0.0, matches reference
        out[OFF3 + widx] = 1.0f;          // fg: argmax >= 0 always -> all ones (reference quirk)
    }
    float* row = out + OFF1 + (size_t)widx * CC;
    #pragma unroll
    for (int c = lane; c < CC; c += 32)
        row[c] = (c == cls) ? nv : 0.0f;
}

// ---------------- launch: inputs resolved by element count (dict order confirmed) ----------------
extern "C" void kernel_launch(void* const* d_in, const int* in_sizes, int n_in,
                              void* d_out, int out_size) {
    int i_scores = -1, i_dec = -1, i_anch = -1, i_gtb = -1;
    int small[3]; int nsmall = 0;
    for (int i = 0; i < n_in; i++) {
        switch (in_sizes[i]) {
            case BB*AA*CC: i_scores = i; break;      // 10752000
            case BB*AA*4:  i_dec    = i; break;      // 537600
            case AA*2:     i_anch   = i; break;      // 16800
            case BB*GG*4:  i_gtb    = i; break;      // 4096
            case BB*GG:    if (nsmall < 3) small[nsmall++] = i; break;  // 1024 x3
            default: break;                          // distances (134400) unused
        }
    }
    int i_glab, i_gdist, i_gmask;
    if (i_gtb == 5) {              // dict order: gt_labels, gt_bboxes, gt_distances, gt_mask
        i_glab  = small[0];
        i_gdist = small[1];
        i_gmask = small[2];
    } else {                       // alphabetical: gt_distances, gt_labels, gt_mask
        i_gdist = small[0];
        i_glab  = small[1];
        i_gmask = small[2];
    }

    const float*  scores  = (const float*)d_in[i_scores];
    const float4* dec     = (const float4*)d_in[i_dec];
    const float2* anchors = (const float2*)d_in[i_anch];
    const float4* gtb     = (const float4*)d_in[i_gtb];
    const int*    glab    = (const int*)d_in[i_glab];
    const float*  gdist   = (const float*)d_in[i_gdist];
    const void*   gmask   = d_in[i_gmask];
    float* out = (float*)d_out;

    k_init0<<<1, 32>>>();
    k_init<<<(BB*AA + 255) / 256, 256>>>((const unsigned*)gmask);
    k_phaseA<<<dim3((AA + 255) / 256, (BB*GG) / 128), 256>>>(gtb, gmask, anchors);
    k_phaseB<<<(BB*GG) / 4, 128>>>(scores, dec, gtb, glab);
    k_final<<<(BB*AA * 32 + 255) / 256, 256>>>(out, gtb, glab, gdist);
}

// round 5
// speedup vs baseline: 1.4810x; 1.4810x over previous
#include <cuda_runtime.h>
#include <cuda_bf16.h>
#include <cstdint>

// Problem constants
#define BB 16
#define AA 8400
#define GG 64
#define CC 80
#define KK 10
#define CAP 768            // max positive-align candidates per (b,g)

#define EPSF 1e-9f
#define CPI  0.4052847345693511f   // 4 / pi^2

// Output layout (flattened tuple, float32)
#define OFF0 0
#define OFF1 (BB*AA*4)                 // cls_oh start
#define OFF2 (OFF1 + BB*AA*CC)         // dist start
#define OFF3 (OFF2 + BB*AA)            // fg start

// ---------------- scratch ----------------
__device__ int                g_cnt[BB*GG];
__device__ unsigned long long g_ckey[BB*GG*CAP];   // (align_bits<<32)|(~anchor)  ~6MB
__device__ float              g_covl[BB*GG*CAP];   // ciou per candidate          ~3MB
__device__ unsigned long long g_key[BB*AA];        // per-anchor (ovl_bits<<32)|(~g)
__device__ float              g_norm[BB*AA];
__device__ int                g_maskmode;          // 2=bytes, else 32-bit words

__global__ void k_init0() { g_maskmode = 0; }

// init + mask-dtype sniffer (bool stored as uint8 / int32 / float32)
__global__ void k_init(const unsigned* __restrict__ mask_words) {
    int i = blockIdx.x * blockDim.x + threadIdx.x;
    if (i < BB*AA) { g_key[i] = 0ULL; g_norm[i] = 0.0f; }
    if (i < BB*GG) g_cnt[i] = 0;
    if (i < 256) {
        unsigned w = mask_words[i];
        bool isf32   = (w == 0x3F800000u);
        bool isbytes = (w > 1u) && !isf32;
        unsigned bf = __ballot_sync(0xFFFFFFFFu, isbytes);
        unsigned ff = __ballot_sync(0xFFFFFFFFu, isf32);
        if ((i & 31) == 0) {
            if (ff) atomicExch(&g_maskmode, 1);
            else if (bf) atomicOr(&g_maskmode, 2);
        }
    }
}

// ---------------- phase A (fused): inside filter + CIoU + align ----------------
// grid: (ceil(A/128), B), block 128. Coalesced dec loads; smem GT tables.
__global__ void k_phaseA(const float4* __restrict__ gtb,
                         const void* __restrict__ gmask,
                         const float2* __restrict__ anchors,
                         const float4* __restrict__ dec,
                         const float* __restrict__ scores,
                         const int* __restrict__ glab) {
    __shared__ float4 sb[GG];     // gt box (poisoned if masked)
    __shared__ float4 sp[GG];     // (at1, sx, sy, w1h1)
    __shared__ int    slab[GG];
    int tid = threadIdx.x;
    int b = blockIdx.y;
    if (tid < GG) {
        int bg = b * GG + tid;
        bool mv;
        if (g_maskmode == 2) mv = ((const unsigned char*)gmask)[bg] != 0;
        else                 mv = ((const unsigned*)gmask)[bg] != 0;
        float4 bx = gtb[bg];
        float w1 = bx.z - bx.x, h1 = bx.w - bx.y;
        sp[tid] = make_float4(atanf(w1 / (h1 + EPSF)), bx.x + bx.z, bx.y + bx.w, w1 * h1);
        slab[tid] = glab[bg];
        if (!mv) bx.x = 3.0e38f;     // inside test always fails
        sb[tid] = bx;
    }
    __syncthreads();
    int a = blockIdx.x * 128 + tid;
    if (a >= AA) return;
    float2 an = anchors[a];
    float4 d = dec[(size_t)b * AA + a];          // coalesced
    float w2 = d.z - d.x, h2 = d.w - d.y;
    float at2 = 0.0f; bool have_at2 = false;
    const float* srow = scores + ((size_t)b * AA + a) * CC;

    for (int g = 0; g < GG; g++) {
        float4 bx = sb[g];
        if (!(bx.x < an.x && bx.y < an.y && bx.z > an.x && bx.w > an.y)) continue;
        float4 pp = sp[g];
        float xx1 = fmaxf(bx.x, d.x), yy1 = fmaxf(bx.y, d.y);
        float xx2 = fminf(bx.z, d.z), yy2 = fminf(bx.w, d.w);
        float inter = fmaxf(xx2 - xx1, 0.0f) * fmaxf(yy2 - yy1, 0.0f);
        float uni = pp.w + w2 * h2 - inter;
        float iou = inter / (uni + EPSF);
        float cw = fmaxf(bx.z, d.z) - fminf(bx.x, d.x);
        float ch = fmaxf(bx.w, d.w) - fminf(bx.y, d.y);
        float c2 = cw * cw + ch * ch + EPSF;
        float dx = pp.y - d.x - d.z, dy = pp.z - d.y - d.w;
        float rho2 = (dx * dx + dy * dy) * 0.25f;
        if (!have_at2) { at2 = atanf(w2 / (h2 + EPSF)); have_at2 = true; }
        float dv = pp.x - at2;
        float v = CPI * dv * dv;
        float aco = v / (v - iou + 1.0f + EPSF);
        float ciou = iou - (rho2 / c2 + v * aco);
        if (ciou <= 0.0f) continue;
        float s = srow[slab[g]];
        float p3 = ciou * ciou * ciou;
        float alval = sqrtf(s) * p3 * p3;          // s^0.5 * relu(ciou)^6
        if (alval <= 0.0f) continue;
        int bg = b * GG + g;
        int pos = atomicAdd(&g_cnt[bg], 1);
        if (pos < CAP) {
            g_ckey[bg * CAP + pos] = ((unsigned long long)__float_as_uint(alval) << 32)
                                   | (unsigned long long)(0xFFFFFFFFu - (unsigned)a);
            g_covl[bg * CAP + pos] = ciou;
        }
    }
}

// ---------------- phase B: warp top-K over precomputed keys + scatter ----------------
__global__ void k_phaseB() {
    int wid = (blockIdx.x * blockDim.x + threadIdx.x) >> 5;
    if (wid >= BB*GG) return;
    int lane = threadIdx.x & 31;
    int b = wid / GG, g = wid % GG;
    int n = g_cnt[wid];
    if (n > CAP) n = CAP;
    if (n == 0) return;

    unsigned long long lk[24]; float lo[24];
    int m = 0;
    for (int idx = lane; idx < n; idx += 32) {
        lk[m] = g_ckey[wid * CAP + idx];
        lo[m] = g_covl[wid * CAP + idx];
        m++;
    }

    float sel_v = 0.0f, sel_o = 0.0f; int sel_a = -1;
    int nsel = 0;
    for (int k = 0; k < KK; k++) {
        unsigned long long bk = 0ULL; int bi = -1;
        for (int i = 0; i < m; i++)
            if (lk[i] > bk) { bk = lk[i]; bi = i; }
        unsigned long long wkey = bk;
        #pragma unroll
        for (int off = 16; off; off >>= 1) {
            unsigned long long o = __shfl_xor_sync(0xFFFFFFFFu, wkey, off);
            if (o > wkey) wkey = o;
        }
        if (wkey == 0ULL) break;
        bool iswin = (bk == wkey && bi >= 0);
        if (iswin) lk[bi] = 0ULL;
        unsigned wl = __ballot_sync(0xFFFFFFFFu, iswin);
        int wlane = __ffs(wl) - 1;
        int wbi = __shfl_sync(0xFFFFFFFFu, bi, wlane);
        float wo = __shfl_sync(0xFFFFFFFFu, (bi >= 0) ? lo[(bi < 0) ? 0 : bi] : 0.0f, wlane);
        (void)wbi;
        if (lane == k) {
            sel_v = __uint_as_float((unsigned)(wkey >> 32));
            sel_a = (int)(0xFFFFFFFFu - (unsigned)(wkey & 0xFFFFFFFFull));
            sel_o = wo;
        }
        nsel = k + 1;
    }
    if (nsel == 0) return;

    float max_align = __shfl_sync(0xFFFFFFFFu, sel_v, 0);
    float mo = (lane < nsel) ? sel_o : 0.0f;
    #pragma unroll
    for (int off = 16; off; off >>= 1)
        mo = fmaxf(mo, __shfl_xor_sync(0xFFFFFFFFu, mo, off));

    if (lane < nsel) {
        float nc = sel_v * mo / (max_align + EPSF);
        atomicMax((int*)&g_norm[b * AA + sel_a], __float_as_int(nc));
        unsigned long long mk = ((unsigned long long)__float_as_uint(sel_o) << 32)
                              | (unsigned long long)(0xFFFFFFFFu - (unsigned)g);
        atomicMax(&g_key[b * AA + sel_a], mk);
    }
}

// ---------------- finalize: one warp per anchor, float4 stores ----------------
__global__ void k_final(float* __restrict__ out,
                        const float4* __restrict__ gtb,
                        const int* __restrict__ glab,
                        const float* __restrict__ gdist) {
    int widx = (blockIdx.x * blockDim.x + threadIdx.x) >> 5;
    if (widx >= BB*AA) return;
    int lane = threadIdx.x & 31;
    int b = widx / AA;

    unsigned long long key = 0ULL; float nv = 0.0f;
    if (lane == 0) { key = g_key[widx]; nv = g_norm[widx]; }
    key = __shfl_sync(0xFFFFFFFFu, key, 0);
    nv  = __shfl_sync(0xFFFFFFFFu, nv, 0);

    bool matched = (key != 0ULL);
    int g = matched ? (int)(0xFFFFFFFFu - (unsigned)(key & 0xFFFFFFFFull)) : 0;
    int cls = matched ? glab[b * GG + g] : -1;

    if (lane == 0) {
        float4 bb = make_float4(-1.f, -1.f, -1.f, -1.f);
        float gd = -1.0f;
        if (matched) { bb = gtb[b * GG + g]; gd = gdist[b * GG + g]; }
        ((float4*)(out + OFF0))[widx] = bb;
        out[OFF2 + widx] = gd * nv;       // unmatched: -1*0 = -0.0 == reference
        out[OFF3 + widx] = 1.0f;          // fg: argmax>=0 always
    }
    if (lane < CC / 4) {
        int c0 = lane * 4;
        float4 v = make_float4(c0 == cls ? nv : 0.0f,
                               c0 + 1 == cls ? nv : 0.0f,
                               c0 + 2 == cls ? nv : 0.0f,
                               c0 + 3 == cls ? nv : 0.0f);
        ((float4*)(out + OFF1 + (size_t)widx * CC))[lane] = v;
    }
}

// ---------------- launch ----------------
extern "C" void kernel_launch(void* const* d_in, const int* in_sizes, int n_in,
                              void* d_out, int out_size) {
    int i_scores = -1, i_dec = -1, i_anch = -1, i_gtb = -1;
    int small[3]; int nsmall = 0;
    for (int i = 0; i < n_in; i++) {
        switch (in_sizes[i]) {
            case BB*AA*CC: i_scores = i; break;
            case BB*AA*4:  i_dec    = i; break;
            case AA*2:     i_anch   = i; break;
            case BB*GG*4:  i_gtb    = i; break;
            case BB*GG:    if (nsmall < 3) small[nsmall++] = i; break;
            default: break;   // distances unused
        }
    }
    int i_glab, i_gdist, i_gmask;
    if (i_gtb == 5) { i_glab = small[0]; i_gdist = small[1]; i_gmask = small[2]; }
    else            { i_gdist = small[0]; i_glab = small[1]; i_gmask = small[2]; }

    const float*  scores  = (const float*)d_in[i_scores];
    const float4* dec     = (const float4*)d_in[i_dec];
    const float2* anchors = (const float2*)d_in[i_anch];
    const float4* gtb     = (const float4*)d_in[i_gtb];
    const int*    glab    = (const int*)d_in[i_glab];
    const float*  gdist   = (const float*)d_in[i_gdist];
    const void*   gmask   = d_in[i_gmask];
    float* out = (float*)d_out;

    k_init0<<<1, 32>>>();
    k_init<<<(BB*AA + 255) / 256, 256>>>((const unsigned*)gmask);
    k_phaseA<<<dim3((AA + 127) / 128, BB), 128>>>(gtb, gmask, anchors, dec, scores, glab);
    k_phaseB<<<(BB*GG) / 4, 128>>>();
    k_final<<<(BB*AA * 32 + 255) / 256, 256>>>(out, gtb, glab, gdist);
}

// round 6
// speedup vs baseline: 2.1165x; 1.4291x over previous
#include <cuda_runtime.h>
#include <cuda_bf16.h>
#include <cstdint>

// Problem constants
#define BB 16
#define AA 8400
#define GG 64
#define CC 80
#define KK 10
#define CAP 512            // max positive-align candidates per (b,g); worst-case n ~325

#define EPSF 1e-9f
#define CPI  0.4052847345693511f   // 4 / pi^2

// Output layout (flattened tuple, float32)
#define OFF0 0
#define OFF1 (BB*AA*4)                 // cls_oh start
#define OFF2 (OFF1 + BB*AA*CC)         // dist start
#define OFF3 (OFF2 + BB*AA)            // fg start

// ---------------- scratch ----------------
__device__ int                g_cnt[BB*GG];
__device__ unsigned long long g_ckey[BB*GG*CAP];   // (align_bits<<32)|(~anchor)
__device__ float              g_covl[BB*GG*CAP];   // ciou per candidate
__device__ unsigned long long g_key[BB*AA];        // per-anchor (ovl_bits<<32)|(~g)
__device__ float              g_norm[BB*AA];
__device__ int                g_maskmode = 0;      // 2=bytes, else 32-bit words (idempotent sniff)

// init + mask-dtype sniffer (bool stored as uint8 / int32 / float32).
// Sniff atomics are idempotent across graph replays: same data -> same fixed point.
__global__ void k_init(const unsigned* __restrict__ mask_words) {
    int i = blockIdx.x * blockDim.x + threadIdx.x;
    if (i < BB*AA) { g_key[i] = 0ULL; g_norm[i] = 0.0f; }
    if (i < BB*GG) g_cnt[i] = 0;
    if (i < 256) {
        unsigned w = mask_words[i];
        bool isf32   = (w == 0x3F800000u);
        bool isbytes = (w > 1u) && !isf32;
        unsigned bf = __ballot_sync(0xFFFFFFFFu, isbytes);
        unsigned ff = __ballot_sync(0xFFFFFFFFu, isf32);
        if ((i & 31) == 0) {
            if (ff) atomicExch(&g_maskmode, 1);
            else if (bf) atomicOr(&g_maskmode, 2);
        }
    }
}

// ---------------- phase A (fused): inside filter (bitmask) + CIoU + align ----------------
// grid: (ceil(A/128), B), block 128
__global__ void k_phaseA(const float4* __restrict__ gtb,
                         const void* __restrict__ gmask,
                         const float2* __restrict__ anchors,
                         const float4* __restrict__ dec,
                         const float* __restrict__ scores,
                         const int* __restrict__ glab) {
    __shared__ float4 sb[GG];     // gt box (poisoned if masked)
    __shared__ float4 sp[GG];     // (at1, sx, sy, w1h1)
    __shared__ int    slab[GG];
    int tid = threadIdx.x;
    int b = blockIdx.y;
    if (tid < GG) {
        int bg = b * GG + tid;
        bool mv;
        if (g_maskmode == 2) mv = ((const unsigned char*)gmask)[bg] != 0;
        else                 mv = ((const unsigned*)gmask)[bg] != 0;
        float4 bx = gtb[bg];
        float w1 = bx.z - bx.x, h1 = bx.w - bx.y;
        sp[tid] = make_float4(atanf(w1 / (h1 + EPSF)), bx.x + bx.z, bx.y + bx.w, w1 * h1);
        slab[tid] = glab[bg];
        if (!mv) bx.x = 3.0e38f;     // inside test always fails
        sb[tid] = bx;
    }
    __syncthreads();
    int a = blockIdx.x * 128 + tid;
    if (a >= AA) return;
    float2 an = anchors[a];
    float4 d = dec[(size_t)b * AA + a];          // coalesced
    float w2 = d.z - d.x, h2 = d.w - d.y;
    float at2 = atanf(w2 / (h2 + EPSF));         // hoisted, unconditional
    const float* srow = scores + ((size_t)b * AA + a) * CC;

    // Pass 1: pure inside-test, accumulate 64-bit hit mask (no divergence, high MLP)
    unsigned long long hits = 0ULL;
    #pragma unroll
    for (int g = 0; g < GG; g++) {
        float4 bx = sb[g];
        bool in = (bx.x < an.x) & (bx.y < an.y) & (bx.z > an.x) & (bx.w > an.y);
        hits |= ((unsigned long long)in) << g;
    }

    // Pass 2: heavy math only on set bits
    while (hits) {
        int g = __ffsll((long long)hits) - 1;
        hits &= hits - 1;
        float4 bx = sb[g];
        float4 pp = sp[g];
        float xx1 = fmaxf(bx.x, d.x), yy1 = fmaxf(bx.y, d.y);
        float xx2 = fminf(bx.z, d.z), yy2 = fminf(bx.w, d.w);
        float inter = fmaxf(xx2 - xx1, 0.0f) * fmaxf(yy2 - yy1, 0.0f);
        float uni = pp.w + w2 * h2 - inter;
        float iou = inter / (uni + EPSF);
        float cw = fmaxf(bx.z, d.z) - fminf(bx.x, d.x);
        float ch = fmaxf(bx.w, d.w) - fminf(bx.y, d.y);
        float c2 = cw * cw + ch * ch + EPSF;
        float dx = pp.y - d.x - d.z, dy = pp.z - d.y - d.w;
        float rho2 = (dx * dx + dy * dy) * 0.25f;
        float dv = pp.x - at2;
        float v = CPI * dv * dv;
        float aco = v / (v - iou + 1.0f + EPSF);
        float ciou = iou - (rho2 / c2 + v * aco);
        if (ciou <= 0.0f) continue;
        float s = srow[slab[g]];
        float p3 = ciou * ciou * ciou;
        float alval = sqrtf(s) * p3 * p3;          // s^0.5 * relu(ciou)^6
        if (alval <= 0.0f) continue;
        int bg = b * GG + g;
        int pos = atomicAdd(&g_cnt[bg], 1);
        if (pos < CAP) {
            g_ckey[bg * CAP + pos] = ((unsigned long long)__float_as_uint(alval) << 32)
                                   | (unsigned long long)(0xFFFFFFFFu - (unsigned)a);
            g_covl[bg * CAP + pos] = ciou;
        }
    }
}

// ---------------- phase B: warp top-K over precomputed keys + scatter ----------------
__global__ void k_phaseB() {
    int wid = (blockIdx.x * blockDim.x + threadIdx.x) >> 5;
    if (wid >= BB*GG) return;
    int lane = threadIdx.x & 31;
    int b = wid / GG, g = wid % GG;
    int n = __ldg(&g_cnt[wid]);
    if (n > CAP) n = CAP;
    if (n == 0) return;

    unsigned long long lk[CAP/32]; float lo[CAP/32];
    int m = 0;
    for (int idx = lane; idx < n; idx += 32) {
        lk[m] = g_ckey[wid * CAP + idx];
        lo[m] = g_covl[wid * CAP + idx];
        m++;
    }

    float sel_v = 0.0f, sel_o = 0.0f; int sel_a = -1;
    int nsel = 0;
    for (int k = 0; k < KK; k++) {
        unsigned long long bk = 0ULL; int bi = -1;
        for (int i = 0; i < m; i++)
            if (lk[i] > bk) { bk = lk[i]; bi = i; }
        unsigned long long wkey = bk;
        #pragma unroll
        for (int off = 16; off; off >>= 1) {
            unsigned long long o = __shfl_xor_sync(0xFFFFFFFFu, wkey, off);
            if (o > wkey) wkey = o;
        }
        if (wkey == 0ULL) break;
        bool iswin = (bk == wkey && bi >= 0);
        if (iswin) lk[bi] = 0ULL;
        unsigned wl = __ballot_sync(0xFFFFFFFFu, iswin);
        int wlane = __ffs(wl) - 1;
        float wo = __shfl_sync(0xFFFFFFFFu, (bi >= 0) ? lo[(bi < 0) ? 0 : bi] : 0.0f, wlane);
        if (lane == k) {
            sel_v = __uint_as_float((unsigned)(wkey >> 32));
            sel_a = (int)(0xFFFFFFFFu - (unsigned)(wkey & 0xFFFFFFFFull));
            sel_o = wo;
        }
        nsel = k + 1;
    }
    if (nsel == 0) return;

    float max_align = __shfl_sync(0xFFFFFFFFu, sel_v, 0);
    float mo = (lane < nsel) ? sel_o : 0.0f;
    #pragma unroll
    for (int off = 16; off; off >>= 1)
        mo = fmaxf(mo, __shfl_xor_sync(0xFFFFFFFFu, mo, off));

    if (lane < nsel) {
        float nc = sel_v * mo / (max_align + EPSF);
        atomicMax((int*)&g_norm[b * AA + sel_a], __float_as_int(nc));
        unsigned long long mk = ((unsigned long long)__float_as_uint(sel_o) << 32)
                              | (unsigned long long)(0xFFFFFFFFu - (unsigned)g);
        atomicMax(&g_key[b * AA + sel_a], mk);
    }
}

// ---------------- finalize: block handles 8 anchors; coalesced small outputs ----------------
// grid: BB*AA/8 = 16800 blocks, 256 threads
__global__ void k_final(float* __restrict__ out,
                        const float4* __restrict__ gtb,
                        const int* __restrict__ glab,
                        const float* __restrict__ gdist) {
    __shared__ unsigned long long skey[8];
    __shared__ float snv[8];
    int tid = threadIdx.x;
    int a0 = blockIdx.x * 8;

    if (tid < 8) {
        skey[tid] = g_key[a0 + tid];
        snv[tid]  = g_norm[a0 + tid];
    }
    __syncthreads();

    // coalesced bbox / dist / fg by threads 0..7
    if (tid < 8) {
        int widx = a0 + tid;
        int b = widx / AA;
        unsigned long long key = skey[tid];
        float nv = snv[tid];
        bool matched = (key != 0ULL);
        int g = matched ? (int)(0xFFFFFFFFu - (unsigned)(key & 0xFFFFFFFFull)) : 0;
        float4 bb = make_float4(-1.f, -1.f, -1.f, -1.f);
        float gd = -1.0f;
        if (matched) { bb = gtb[b * GG + g]; gd = gdist[b * GG + g]; }
        ((float4*)(out + OFF0))[widx] = bb;
        out[OFF2 + widx] = gd * nv;       // unmatched: -1*0 = -0.0 == reference
        out[OFF3 + widx] = 1.0f;          // fg: argmax>=0 always
    }

    // cls_oh rows: one warp per anchor, float4 stores
    int wi = tid >> 5, lane = tid & 31;
    int widx = a0 + wi;
    int b = widx / AA;
    unsigned long long key = skey[wi];
    float nv = snv[wi];
    bool matched = (key != 0ULL);
    int g = matched ? (int)(0xFFFFFFFFu - (unsigned)(key & 0xFFFFFFFFull)) : 0;
    int cls = matched ? glab[b * GG + g] : -1;
    if (lane < CC / 4) {
        int c0 = lane * 4;
        float4 v = make_float4(c0 == cls ? nv : 0.0f,
                               c0 + 1 == cls ? nv : 0.0f,
                               c0 + 2 == cls ? nv : 0.0f,
                               c0 + 3 == cls ? nv : 0.0f);
        ((float4*)(out + OFF1 + (size_t)widx * CC))[lane] = v;
    }
}

// ---------------- launch ----------------
extern "C" void kernel_launch(void* const* d_in, const int* in_sizes, int n_in,
                              void* d_out, int out_size) {
    int i_scores = -1, i_dec = -1, i_anch = -1, i_gtb = -1;
    int small[3]; int nsmall = 0;
    for (int i = 0; i < n_in; i++) {
        switch (in_sizes[i]) {
            case BB*AA*CC: i_scores = i; break;
            case BB*AA*4:  i_dec    = i; break;
            case AA*2:     i_anch   = i; break;
            case BB*GG*4:  i_gtb    = i; break;
            case BB*GG:    if (nsmall < 3) small[nsmall++] = i; break;
            default: break;   // distances unused
        }
    }
    int i_glab, i_gdist, i_gmask;
    if (i_gtb == 5) { i_glab = small[0]; i_gdist = small[1]; i_gmask = small[2]; }
    else            { i_gdist = small[0]; i_glab = small[1]; i_gmask = small[2]; }

    const float*  scores  = (const float*)d_in[i_scores];
    const float4* dec     = (const float4*)d_in[i_dec];
    const float2* anchors = (const float2*)d_in[i_anch];
    const float4* gtb     = (const float4*)d_in[i_gtb];
    const int*    glab    = (const int*)d_in[i_glab];
    const float*  gdist   = (const float*)d_in[i_gdist];
    const void*   gmask   = d_in[i_gmask];
    float* out = (float*)d_out;

    k_init<<<(BB*AA + 255) / 256, 256>>>((const unsigned*)gmask);
    k_phaseA<<<dim3((AA + 127) / 128, BB), 128>>>(gtb, gmask, anchors, dec, scores, glab);
    k_phaseB<<<(BB*GG) / 4, 128>>>();
    k_final<<<(BB*AA) / 8, 256>>>(out, gtb, glab, gdist);
}

// round 7
// speedup vs baseline: 2.4330x; 1.1496x over previous
#include <cuda_runtime.h>
#include <cuda_bf16.h>
#include <cstdint>

// Problem constants
#define BB 16
#define AA 8400
#define GG 64
#define CC 80
#define KK 10
#define CAP 512            // max positive-align candidates per (b,g); worst-case n ~325

#define EPSF 1e-9f
#define CPI  0.4052847345693511f   // 4 / pi^2

// Output layout (flattened tuple, float32)
#define OFF0 0
#define OFF1 (BB*AA*4)                 // cls_oh start
#define OFF2 (OFF1 + BB*AA*CC)         // dist start
#define OFF3 (OFF2 + BB*AA)            // fg start

// ---------------- scratch ----------------
__device__ int                g_cnt[BB*GG];
__device__ unsigned long long g_ckey[BB*GG*CAP];   // (align_bits<<32)|(~anchor)
__device__ float              g_covl[BB*GG*CAP];   // ciou per candidate
__device__ unsigned long long g_key[BB*AA];        // per-anchor (ovl_bits<<32)|(~g)
__device__ float              g_norm[BB*AA];
__device__ int                g_maskmode = 0;      // 2=bytes, else 32-bit words (idempotent sniff)

// init: zero scratch, sniff mask dtype, zero-fill cls_oh, fill fg=1.0
// grid: 2625 blocks x 256 (672000 threads)
__global__ void k_init(const unsigned* __restrict__ mask_words, float* __restrict__ out) {
    int i = blockIdx.x * blockDim.x + threadIdx.x;
    int nthr = gridDim.x * blockDim.x;
    if (i < BB*AA) { g_key[i] = 0ULL; g_norm[i] = 0.0f; }
    if (i < BB*GG) g_cnt[i] = 0;
    if (i < 256) {
        unsigned w = mask_words[i];
        bool isf32   = (w == 0x3F800000u);
        bool isbytes = (w > 1u) && !isf32;
        unsigned bf = __ballot_sync(0xFFFFFFFFu, isbytes);
        unsigned ff = __ballot_sync(0xFFFFFFFFu, isf32);
        if ((i & 31) == 0) {
            if (ff) atomicExch(&g_maskmode, 1);
            else if (bf) atomicOr(&g_maskmode, 2);
        }
    }
    // cls_oh <- 0 (43 MB, pure STG.128 stream; scatter pass overwrites single elems later)
    float4 z = make_float4(0.f, 0.f, 0.f, 0.f);
    float4* cls4 = (float4*)(out + OFF1);
    #pragma unroll 4
    for (int j = i; j < (BB*AA*CC) / 4; j += nthr) cls4[j] = z;
    // fg <- 1.0 (argmax >= 0 always in reference)
    for (int j = i; j < BB*AA; j += nthr) out[OFF3 + j] = 1.0f;
}

// ---------------- phase A (fused): inside filter (bitmask) + CIoU + align ----------------
// grid: (ceil(A/128), B), block 128
__global__ void k_phaseA(const float4* __restrict__ gtb,
                         const void* __restrict__ gmask,
                         const float2* __restrict__ anchors,
                         const float4* __restrict__ dec,
                         const float* __restrict__ scores,
                         const int* __restrict__ glab) {
    __shared__ float4 sb[GG];     // gt box (poisoned if masked)
    __shared__ float4 sp[GG];     // (at1, sx, sy, w1h1)
    __shared__ int    slab[GG];
    int tid = threadIdx.x;
    int b = blockIdx.y;
    if (tid < GG) {
        int bg = b * GG + tid;
        bool mv;
        if (g_maskmode == 2) mv = ((const unsigned char*)gmask)[bg] != 0;
        else                 mv = ((const unsigned*)gmask)[bg] != 0;
        float4 bx = gtb[bg];
        float w1 = bx.z - bx.x, h1 = bx.w - bx.y;
        sp[tid] = make_float4(atanf(w1 / (h1 + EPSF)), bx.x + bx.z, bx.y + bx.w, w1 * h1);
        slab[tid] = glab[bg];
        if (!mv) bx.x = 3.0e38f;     // inside test always fails
        sb[tid] = bx;
    }
    __syncthreads();
    int a = blockIdx.x * 128 + tid;
    if (a >= AA) return;
    float2 an = anchors[a];
    float4 d = dec[(size_t)b * AA + a];          // coalesced
    float w2 = d.z - d.x, h2 = d.w - d.y;
    float at2 = atanf(w2 / (h2 + EPSF));         // hoisted, unconditional
    const float* srow = scores + ((size_t)b * AA + a) * CC;

    // Pass 1: pure inside-test, accumulate 64-bit hit mask (no divergence, high MLP)
    unsigned long long hits = 0ULL;
    #pragma unroll
    for (int g = 0; g < GG; g++) {
        float4 bx = sb[g];
        bool in = (bx.x < an.x) & (bx.y < an.y) & (bx.z > an.x) & (bx.w > an.y);
        hits |= ((unsigned long long)in) << g;
    }

    // Pass 2: heavy math only on set bits
    while (hits) {
        int g = __ffsll((long long)hits) - 1;
        hits &= hits - 1;
        float4 bx = sb[g];
        float4 pp = sp[g];
        float xx1 = fmaxf(bx.x, d.x), yy1 = fmaxf(bx.y, d.y);
        float xx2 = fminf(bx.z, d.z), yy2 = fminf(bx.w, d.w);
        float inter = fmaxf(xx2 - xx1, 0.0f) * fmaxf(yy2 - yy1, 0.0f);
        float uni = pp.w + w2 * h2 - inter;
        float iou = inter / (uni + EPSF);
        float cw = fmaxf(bx.z, d.z) - fminf(bx.x, d.x);
        float ch = fmaxf(bx.w, d.w) - fminf(bx.y, d.y);
        float c2 = cw * cw + ch * ch + EPSF;
        float dx = pp.y - d.x - d.z, dy = pp.z - d.y - d.w;
        float rho2 = (dx * dx + dy * dy) * 0.25f;
        float dv = pp.x - at2;
        float v = CPI * dv * dv;
        float aco = v / (v - iou + 1.0f + EPSF);
        float ciou = iou - (rho2 / c2 + v * aco);
        if (ciou <= 0.0f) continue;
        float s = srow[slab[g]];
        float p3 = ciou * ciou * ciou;
        float alval = sqrtf(s) * p3 * p3;          // s^0.5 * relu(ciou)^6
        if (alval <= 0.0f) continue;
        int bg = b * GG + g;
        int pos = atomicAdd(&g_cnt[bg], 1);
        if (pos < CAP) {
            g_ckey[bg * CAP + pos] = ((unsigned long long)__float_as_uint(alval) << 32)
                                   | (unsigned long long)(0xFFFFFFFFu - (unsigned)a);
            g_covl[bg * CAP + pos] = ciou;
        }
    }
}

// ---------------- phase B: warp top-K over precomputed keys + scatter ----------------
__global__ void k_phaseB() {
    int wid = (blockIdx.x * blockDim.x + threadIdx.x) >> 5;
    if (wid >= BB*GG) return;
    int lane = threadIdx.x & 31;
    int b = wid / GG, g = wid % GG;
    int n = __ldg(&g_cnt[wid]);
    if (n > CAP) n = CAP;
    if (n == 0) return;

    unsigned long long lk[CAP/32]; float lo[CAP/32];
    int m = 0;
    for (int idx = lane; idx < n; idx += 32) {
        lk[m] = g_ckey[wid * CAP + idx];
        lo[m] = g_covl[wid * CAP + idx];
        m++;
    }

    float sel_v = 0.0f, sel_o = 0.0f; int sel_a = -1;
    int nsel = 0;
    for (int k = 0; k < KK; k++) {
        unsigned long long bk = 0ULL; int bi = -1;
        for (int i = 0; i < m; i++)
            if (lk[i] > bk) { bk = lk[i]; bi = i; }
        unsigned long long wkey = bk;
        #pragma unroll
        for (int off = 16; off; off >>= 1) {
            unsigned long long o = __shfl_xor_sync(0xFFFFFFFFu, wkey, off);
            if (o > wkey) wkey = o;
        }
        if (wkey == 0ULL) break;
        bool iswin = (bk == wkey && bi >= 0);
        if (iswin) lk[bi] = 0ULL;
        unsigned wl = __ballot_sync(0xFFFFFFFFu, iswin);
        int wlane = __ffs(wl) - 1;
        float wo = __shfl_sync(0xFFFFFFFFu, (bi >= 0) ? lo[(bi < 0) ? 0 : bi] : 0.0f, wlane);
        if (lane == k) {
            sel_v = __uint_as_float((unsigned)(wkey >> 32));
            sel_a = (int)(0xFFFFFFFFu - (unsigned)(wkey & 0xFFFFFFFFull));
            sel_o = wo;
        }
        nsel = k + 1;
    }
    if (nsel == 0) return;

    float max_align = __shfl_sync(0xFFFFFFFFu, sel_v, 0);
    float mo = (lane < nsel) ? sel_o : 0.0f;
    #pragma unroll
    for (int off = 16; off; off >>= 1)
        mo = fmaxf(mo, __shfl_xor_sync(0xFFFFFFFFu, mo, off));

    if (lane < nsel) {
        float nc = sel_v * mo / (max_align + EPSF);
        atomicMax((int*)&g_norm[b * AA + sel_a], __float_as_int(nc));
        unsigned long long mk = ((unsigned long long)__float_as_uint(sel_o) << 32)
                              | (unsigned long long)(0xFFFFFFFFu - (unsigned)g);
        atomicMax(&g_key[b * AA + sel_a], mk);
    }
}

// ---------------- finalize: one THREAD per anchor; cls_oh via single scattered store ----------------
// grid: ceil(BB*AA/256) blocks x 256
__global__ void k_final(float* __restrict__ out,
                        const float4* __restrict__ gtb,
                        const int* __restrict__ glab,
                        const float* __restrict__ gdist) {
    int i = blockIdx.x * blockDim.x + threadIdx.x;
    if (i >= BB*AA) return;
    unsigned long long key = g_key[i];      // coalesced
    float nv = g_norm[i];                   // coalesced
    int b = i / AA;
    bool matched = (key != 0ULL);
    int g = matched ? (int)(0xFFFFFFFFu - (unsigned)(key & 0xFFFFFFFFull)) : 0;

    float4 bb = make_float4(-1.f, -1.f, -1.f, -1.f);
    float gd = -1.0f;
    if (matched) { bb = gtb[b * GG + g]; gd = gdist[b * GG + g]; }   // 1K-entry tables, L1-hot
    ((float4*)(out + OFF0))[i] = bb;
    out[OFF2 + i] = gd * nv;                // unmatched: -1*0 = -0.0 == reference
    if (matched)
        out[OFF1 + (size_t)i * CC + glab[b * GG + g]] = nv;   // single scattered 4B store
    // fg already 1.0 (k_init); cls_oh zeros already laid down (k_init)
}

// ---------------- launch ----------------
extern "C" void kernel_launch(void* const* d_in, const int* in_sizes, int n_in,
                              void* d_out, int out_size) {
    int i_scores = -1, i_dec = -1, i_anch = -1, i_gtb = -1;
    int small[3]; int nsmall = 0;
    for (int i = 0; i < n_in; i++) {
        switch (in_sizes[i]) {
            case BB*AA*CC: i_scores = i; break;
            case BB*AA*4:  i_dec    = i; break;
            case AA*2:     i_anch   = i; break;
            case BB*GG*4:  i_gtb    = i; break;
            case BB*GG:    if (nsmall < 3) small[nsmall++] = i; break;
            default: break;   // distances unused
        }
    }
    int i_glab, i_gdist, i_gmask;
    if (i_gtb == 5) { i_glab = small[0]; i_gdist = small[1]; i_gmask = small[2]; }
    else            { i_gdist = small[0]; i_glab = small[1]; i_gmask = small[2]; }

    const float*  scores  = (const float*)d_in[i_scores];
    const float4* dec     = (const float4*)d_in[i_dec];
    const float2* anchors = (const float2*)d_in[i_anch];
    const float4* gtb     = (const float4*)d_in[i_gtb];
    const int*    glab    = (const int*)d_in[i_glab];
    const float*  gdist   = (const float*)d_in[i_gdist];
    const void*   gmask   = d_in[i_gmask];
    float* out = (float*)d_out;

    k_init<<<2625, 256>>>((const unsigned*)gmask, out);
    k_phaseA<<<dim3((AA + 127) / 128, BB), 128>>>(gtb, gmask, anchors, dec, scores, glab);
    k_phaseB<<<(BB*GG) / 4, 128>>>();
    k_final<<<(BB*AA + 255) / 256, 256>>>(out, gtb, glab, gdist);
}